// round 3
// baseline (speedup 1.0000x reference)
#include <cuda_runtime.h>
#include <cstdint>
#include <math.h>

#define H      768
#define TT     4
#define NB     64
#define S1     513
#define S      512
#define STARTS 2
#define STOPS  3

// Output layout (float32), reference tuple order:
// isqa_pred(64) | crf_pred(64*512) | isqa_loss(1) | crf_loss(1) | tags(64*512) | IsQA(64)
#define OUT_ISQA_PRED 0
#define OUT_CRF_PRED  64
#define OUT_ISQA_LOSS 32832
#define OUT_CRF_LOSS  32833
#define OUT_TAGS      32834
#define OUT_ISQA      65602

// Static device scratch (no allocation allowed)
__device__ float g_feats[NB * S * TT];   // (b, t, state) float4-aligned rows
__device__ float g_isqa_logits[NB * 2];
__device__ float g_Z[NB];
__device__ float g_gold[NB];

// ---------------------------------------------------------------------------
// Kernel A: feats[b][t][j] = emb[b][t+1] . crf_W[j] + crf_b[j]
//           isqa_logits[b][k] = emb[b][0] . fc2_W[k] + fc2_b[k]
// Warp per row; weights staged in shared once per block; float4 coalesced.
// ---------------------------------------------------------------------------
__global__ void __launch_bounds__(256) featsKernel(
    const float* __restrict__ emb,
    const float* __restrict__ fc2W, const float* __restrict__ fc2b,
    const float* __restrict__ crfW, const float* __restrict__ crfb)
{
    __shared__ float Wsh[8 * H];   // rows 0-3 crf_W, 4-5 fc2_W, 6-7 zero
    __shared__ float bsh[8];
    for (int i = threadIdx.x; i < 8 * H; i += 256) {
        int row = i / H, col = i - row * H;
        float v = 0.f;
        if (row < 4)      v = crfW[i];
        else if (row < 6) v = fc2W[(row - 4) * H + col];
        Wsh[i] = v;
    }
    if (threadIdx.x < 8) {
        int r = threadIdx.x;
        bsh[r] = (r < 4) ? crfb[r] : ((r < 6) ? fc2b[r - 4] : 0.f);
    }
    __syncthreads();

    int warp = threadIdx.x >> 5, lane = threadIdx.x & 31;
    int nwarps = gridDim.x * 8;
    for (int r = blockIdx.x * 8 + warp; r < NB * S1; r += nwarps) {
        int b = r / S1, s = r - b * S1;
        const float4* e4 = (const float4*)(emb + (size_t)r * H);
        int wbase = (s == 0) ? 4 : 0;
        const float4* w0 = (const float4*)(Wsh + (wbase + 0) * H);
        const float4* w1 = (const float4*)(Wsh + (wbase + 1) * H);
        const float4* w2 = (const float4*)(Wsh + (wbase + 2) * H);
        const float4* w3 = (const float4*)(Wsh + (wbase + 3) * H);
        float p0 = 0.f, p1 = 0.f, p2 = 0.f, p3 = 0.f;
        #pragma unroll
        for (int i = 0; i < 6; i++) {
            int idx = lane + 32 * i;
            float4 v = e4[idx];
            float4 a = w0[idx];
            p0 += v.x * a.x + v.y * a.y + v.z * a.z + v.w * a.w;
            float4 c = w1[idx];
            p1 += v.x * c.x + v.y * c.y + v.z * c.z + v.w * c.w;
            float4 d = w2[idx];
            p2 += v.x * d.x + v.y * d.y + v.z * d.z + v.w * d.w;
            float4 e = w3[idx];
            p3 += v.x * e.x + v.y * e.y + v.z * e.z + v.w * e.w;
        }
        #pragma unroll
        for (int off = 16; off; off >>= 1) {
            p0 += __shfl_xor_sync(0xffffffffu, p0, off);
            p1 += __shfl_xor_sync(0xffffffffu, p1, off);
            p2 += __shfl_xor_sync(0xffffffffu, p2, off);
            p3 += __shfl_xor_sync(0xffffffffu, p3, off);
        }
        if (lane == 0) {
            if (s == 0) {
                g_isqa_logits[b * 2 + 0] = p0 + bsh[4];
                g_isqa_logits[b * 2 + 1] = p1 + bsh[5];
            } else {
                float4 o = make_float4(p0 + bsh[0], p1 + bsh[1],
                                       p2 + bsh[2], p3 + bsh[3]);
                ((float4*)g_feats)[b * S + (s - 1)] = o;
            }
        }
    }
}

// ---------------------------------------------------------------------------
// Kernel B: gold score + tags copy. One block per batch.
// ---------------------------------------------------------------------------
__global__ void __launch_bounds__(128) goldKernel(
    const int* __restrict__ asl, const float* __restrict__ trans,
    float* __restrict__ out)
{
    int b = blockIdx.x, tid = threadIdx.x;
    const int* tg = asl + b * S1 + 1;   // tags[b][t] = asl[b][t+1]
    float acc = 0.f;
    for (int t = tid; t < S; t += 128) {
        int tag = tg[t];
        acc += g_feats[(b * S + t) * TT + tag];
        out[OUT_TAGS + b * S + t] = (float)tag;
        if (t < S - 1) acc += trans[tag * TT + tg[t + 1]];
    }
    __shared__ float red[128];
    red[tid] = acc;
    __syncthreads();
    for (int s2 = 64; s2; s2 >>= 1) {
        if (tid < s2) red[tid] += red[tid + s2];
        __syncthreads();
    }
    if (tid == 0) {
        float tr = trans[STARTS * TT + tg[0]] + trans[tg[S - 1] * TT + STOPS];
        g_gold[b] = red[0] + tr;
    }
}

// ---------------------------------------------------------------------------
// Kernel C: fused CRF forward (log-partition) + Viterbi + backtrace.
// One warp per block; 8 batches x 4 states per warp. Feats staged in shared
// (padded stride 33 for conflict-free per-step reads). Natural (ln) domain.
// ---------------------------------------------------------------------------
__global__ void __launch_bounds__(32) scanKernel(
    const float* __restrict__ trans, float* __restrict__ out)
{
    extern __shared__ float fsh[];           // 512 * 33 floats
    __shared__ unsigned bp_s[32 * 32];       // [word w][lane]
    int lane = threadIdx.x;
    int bb = lane >> 2, j = lane & 3;
    int batch = blockIdx.x * 8 + bb;

    // Stage feats for this block's 8 batches into shared
    const float4* gf = (const float4*)g_feats + (size_t)blockIdx.x * 8 * S;
    for (int v = lane; v < 8 * S; v += 32) {
        int bbv = v >> 9, t = v & 511;
        float4 f = gf[v];
        float* d = fsh + t * 33 + bbv * 4;
        d[0] = f.x; d[1] = f.y; d[2] = f.z; d[3] = f.w;
    }

    float tr0 = trans[0 * TT + j];
    float tr1 = trans[1 * TT + j];
    float tr2 = trans[2 * TT + j];
    float tr3 = trans[3 * TT + j];
    float trStart = trans[STARTS * TT + j];
    float trStop  = trans[j * TT + STOPS];
    __syncthreads();

    float alpha = fsh[lane] + trStart;   // t = 0
    float delta = alpha;
    unsigned bpw = 0;
    int qb = lane & ~3;

    for (int t = 1; t < S; ++t) {
        float feat = fsh[t * 33 + lane];
        float a0 = __shfl_sync(0xffffffffu, alpha, qb + 0);
        float a1 = __shfl_sync(0xffffffffu, alpha, qb + 1);
        float a2 = __shfl_sync(0xffffffffu, alpha, qb + 2);
        float a3 = __shfl_sync(0xffffffffu, alpha, qb + 3);
        float d0 = __shfl_sync(0xffffffffu, delta, qb + 0);
        float d1 = __shfl_sync(0xffffffffu, delta, qb + 1);
        float d2 = __shfl_sync(0xffffffffu, delta, qb + 2);
        float d3 = __shfl_sync(0xffffffffu, delta, qb + 3);

        // log-sum-exp shifted by own previous alpha (cross-state spread bounded)
        float m = alpha;
        float e0 = __expf(a0 + tr0 - m);
        float e1 = __expf(a1 + tr1 - m);
        float e2 = __expf(a2 + tr2 - m);
        float e3 = __expf(a3 + tr3 - m);
        alpha = m + __logf((e0 + e1) + (e2 + e3)) + feat;

        // Viterbi max-plus with first-max-index tie-break (ascending i)
        float v0 = d0 + tr0, v1 = d1 + tr1, v2 = d2 + tr2, v3 = d3 + tr3;
        float best = v0; int bi = 0;
        if (v1 > best) { best = v1; bi = 1; }
        if (v2 > best) { best = v2; bi = 2; }
        if (v3 > best) { best = v3; bi = 3; }
        delta = best + feat;

        bpw |= (unsigned)bi << ((t & 15) * 2);
        if ((t & 15) == 15) { bp_s[(t >> 4) * 32 + lane] = bpw; bpw = 0; }
    }

    // last_tag = argmax_j(delta + trans[j, STOP]) (lowest index on tie)
    float score = delta + trStop;
    int bi = j;
    #pragma unroll
    for (int off = 1; off < 4; off <<= 1) {
        float o = __shfl_xor_sync(0xffffffffu, score, off);
        int  oi = __shfl_xor_sync(0xffffffffu, bi, off);
        if (o > score || (o == score && oi < bi)) { score = o; bi = oi; }
    }

    // Z = logsumexp_j(alpha + trans[j, STOP])
    float zs = alpha + trStop;
    float mz = zs;
    mz = fmaxf(mz, __shfl_xor_sync(0xffffffffu, mz, 1));
    mz = fmaxf(mz, __shfl_xor_sync(0xffffffffu, mz, 2));
    float ez = __expf(zs - mz);
    ez += __shfl_xor_sync(0xffffffffu, ez, 1);
    ez += __shfl_xor_sync(0xffffffffu, ez, 2);
    if (j == 0) g_Z[batch] = mz + __logf(ez);

    __syncwarp();

    // Backtrace: 8 lanes (one per batch), chunked: one LDS.128 per 16 steps.
    if (j == 0) {
        int cur = bi;
        float* op = out + OUT_CRF_PRED + (size_t)batch * S;
        op[S - 1] = (float)cur;
        for (int w = 31; w >= 0; --w) {
            const uint4 ws = *(const uint4*)&bp_s[w * 32 + bb * 4];
            #pragma unroll
            for (int k = 15; k >= 0; --k) {
                int t = w * 16 + k;
                if (t == 0) break;
                unsigned word = (cur == 0) ? ws.x : (cur == 1) ? ws.y
                              : (cur == 2) ? ws.z : ws.w;
                cur = (word >> (2 * k)) & 3;
                op[t - 1] = (float)cur;
            }
        }
    }
}

// ---------------------------------------------------------------------------
// Kernel D: CLS head + final loss reductions + IsQA copy.
// ---------------------------------------------------------------------------
__global__ void __launch_bounds__(64) finalKernel(
    const int* __restrict__ isqa_in, float* __restrict__ out)
{
    int b = threadIdx.x;
    float l0 = g_isqa_logits[b * 2 + 0];
    float l1 = g_isqa_logits[b * 2 + 1];
    float m = fmaxf(l0, l1);
    float lse = m + __logf(__expf(l0 - m) + __expf(l1 - m));
    int y = isqa_in[b];
    float lossc = -(((y != 0) ? l1 : l0) - lse);
    int pred = (l1 > l0) ? 1 : 0;
    out[OUT_ISQA_PRED + b] = (float)pred;
    out[OUT_ISQA + b] = (float)y;

    float crfc = g_Z[b] - g_gold[b];

    __shared__ float r1[64], r2[64];
    r1[b] = lossc; r2[b] = crfc;
    __syncthreads();
    for (int s2 = 32; s2; s2 >>= 1) {
        if (b < s2) { r1[b] += r1[b + s2]; r2[b] += r2[b + s2]; }
        __syncthreads();
    }
    if (b == 0) {
        out[OUT_ISQA_LOSS] = r1[0] * (1.f / 64.f);
        out[OUT_CRF_LOSS]  = r2[0] * (1.f / 64.f);
    }
}

// ---------------------------------------------------------------------------
extern "C" void kernel_launch(void* const* d_in, const int* in_sizes, int n_in,
                              void* d_out, int out_size)
{
    const float* emb   = (const float*)d_in[0];
    const int*   asl   = (const int*)  d_in[1];
    const int*   isqa  = (const int*)  d_in[2];
    const float* fc2W  = (const float*)d_in[3];
    const float* fc2b  = (const float*)d_in[4];
    const float* crfW  = (const float*)d_in[5];
    const float* crfb  = (const float*)d_in[6];
    const float* trans = (const float*)d_in[7];
    float* out = (float*)d_out;

    cudaFuncSetAttribute(scanKernel,
                         cudaFuncAttributeMaxDynamicSharedMemorySize,
                         512 * 33 * 4);

    featsKernel<<<592, 256>>>(emb, fc2W, fc2b, crfW, crfb);
    goldKernel<<<64, 128>>>(asl, trans, out);
    scanKernel<<<8, 32, 512 * 33 * 4>>>(trans, out);
    finalKernel<<<1, 64>>>(isqa, out);
}

// round 5
// speedup vs baseline: 1.2080x; 1.2080x over previous
#include <cuda_runtime.h>
#include <cstdint>
#include <math.h>

#define H      768
#define TT     4
#define NB     64
#define S1     513
#define S      512
#define STARTS 2
#define STOPS  3

// Output layout (float32), reference tuple order:
// isqa_pred(64) | crf_pred(64*512) | isqa_loss(1) | crf_loss(1) | tags(64*512) | IsQA(64)
#define OUT_ISQA_PRED 0
#define OUT_CRF_PRED  64
#define OUT_ISQA_LOSS 32832
#define OUT_CRF_LOSS  32833
#define OUT_TAGS      32834
#define OUT_ISQA      65602

// Static device scratch (no allocation allowed)
__device__ float    g_feats[NB * S * TT];   // (b, t, state), float4 per (b,t)
__device__ float    g_isqa_logits[NB * 2];
__device__ float    g_accCrf, g_accIsqa;
__device__ unsigned g_cnt;

// ---------------------------------------------------------------------------
// Kernel A: feats[b][t][j] = emb[b][t+1] . crf_W[j] + crf_b[j]
//           isqa_logits[b][k] = emb[b][0] . fc2_W[k] + fc2_b[k]
// Warp per row; weights staged in shared once per block; float4 coalesced.
// Also resets the cross-kernel accumulators for this replay.
// ---------------------------------------------------------------------------
__global__ void __launch_bounds__(256) featsKernel(
    const float* __restrict__ emb,
    const float* __restrict__ fc2W, const float* __restrict__ fc2b,
    const float* __restrict__ crfW, const float* __restrict__ crfb)
{
    if (blockIdx.x == 0 && threadIdx.x == 0) {
        g_cnt = 0u; g_accCrf = 0.f; g_accIsqa = 0.f;
    }

    __shared__ float Wsh[8 * H];   // rows 0-3 crf_W, 4-5 fc2_W, 6-7 zero
    __shared__ float bsh[8];
    for (int i = threadIdx.x; i < 8 * H; i += 256) {
        int row = i / H, col = i - row * H;
        float v = 0.f;
        if (row < 4)      v = crfW[i];
        else if (row < 6) v = fc2W[(row - 4) * H + col];
        Wsh[i] = v;
    }
    if (threadIdx.x < 8) {
        int r = threadIdx.x;
        bsh[r] = (r < 4) ? crfb[r] : ((r < 6) ? fc2b[r - 4] : 0.f);
    }
    __syncthreads();

    int warp = threadIdx.x >> 5, lane = threadIdx.x & 31;
    int nwarps = gridDim.x * 8;
    for (int r = blockIdx.x * 8 + warp; r < NB * S1; r += nwarps) {
        int b = r / S1, s = r - b * S1;
        const float4* e4 = (const float4*)(emb + (size_t)r * H);
        int wbase = (s == 0) ? 4 : 0;
        const float4* w0 = (const float4*)(Wsh + (wbase + 0) * H);
        const float4* w1 = (const float4*)(Wsh + (wbase + 1) * H);
        const float4* w2 = (const float4*)(Wsh + (wbase + 2) * H);
        const float4* w3 = (const float4*)(Wsh + (wbase + 3) * H);
        float p0 = 0.f, p1 = 0.f, p2 = 0.f, p3 = 0.f;
        #pragma unroll
        for (int i = 0; i < 6; i++) {
            int idx = lane + 32 * i;
            float4 v = e4[idx];
            float4 a = w0[idx];
            p0 += v.x * a.x + v.y * a.y + v.z * a.z + v.w * a.w;
            float4 c = w1[idx];
            p1 += v.x * c.x + v.y * c.y + v.z * c.z + v.w * c.w;
            float4 d = w2[idx];
            p2 += v.x * d.x + v.y * d.y + v.z * d.z + v.w * d.w;
            float4 e = w3[idx];
            p3 += v.x * e.x + v.y * e.y + v.z * e.z + v.w * e.w;
        }
        #pragma unroll
        for (int off = 16; off; off >>= 1) {
            p0 += __shfl_xor_sync(0xffffffffu, p0, off);
            p1 += __shfl_xor_sync(0xffffffffu, p1, off);
            p2 += __shfl_xor_sync(0xffffffffu, p2, off);
            p3 += __shfl_xor_sync(0xffffffffu, p3, off);
        }
        if (lane == 0) {
            if (s == 0) {
                g_isqa_logits[b * 2 + 0] = p0 + bsh[4];
                g_isqa_logits[b * 2 + 1] = p1 + bsh[5];
            } else {
                float4 o = make_float4(p0 + bsh[0], p1 + bsh[1],
                                       p2 + bsh[2], p3 + bsh[3]);
                ((float4*)g_feats)[b * S + (s - 1)] = o;
            }
        }
    }
}

// ---------------------------------------------------------------------------
// Kernel B: fused CRF forward (linear-domain log-partition) + Viterbi +
// backtrace + gold score + tags copy + all loss reductions + CLS head.
// 8 blocks x 320 threads. Per block (8 batches):
//   warp 0: forward recurrence (linear domain, power-of-2 renorm) -> Z
//   warp 1: Viterbi (log domain, matches reference rounding) + backtrace
//   warps 2-9: gold score + tags for batch (warp-2)
// Feats staged in shared: log copy + exp copy, stride 33 (conflict-free).
// ---------------------------------------------------------------------------
#define SCAN_SMEM ((2 * 512 * 33 + 1024) * 4)

__global__ void __launch_bounds__(320) scanKernel(
    const float* __restrict__ trans,
    const int*   __restrict__ asl,
    const int*   __restrict__ isqa_in,
    float* __restrict__ out)
{
    extern __shared__ float sm[];
    float*    fshL = sm;                             // 512*33 log feats
    float*    fshE = sm + 512 * 33;                  // 512*33 exp feats
    unsigned* bp_s = (unsigned*)(sm + 2 * 512 * 33); // 32 words x 32 lanes
    __shared__ float zsh[8], gsh[8];

    int tid  = threadIdx.x;
    int warp = tid >> 5, lane = tid & 31;

    // Stage feats for this block's 8 batches (all 10 warps cooperate)
    const float4* gf = (const float4*)g_feats + (size_t)blockIdx.x * 8 * S;
    for (int v = tid; v < 8 * S; v += 320) {
        int bbv = v >> 9, t = v & 511;
        float4 f = gf[v];
        int base = t * 33 + bbv * 4;
        fshL[base + 0] = f.x; fshL[base + 1] = f.y;
        fshL[base + 2] = f.z; fshL[base + 3] = f.w;
        fshE[base + 0] = __expf(f.x); fshE[base + 1] = __expf(f.y);
        fshE[base + 2] = __expf(f.z); fshE[base + 3] = __expf(f.w);
    }
    __syncthreads();

    if (warp == 0) {
        // ------------------- forward (linear domain) -------------------
        int bb = lane >> 2, j = lane & 3, qb = lane & ~3;
        float E0 = __expf(trans[0 * TT + j]);
        float E1 = __expf(trans[1 * TT + j]);
        float E2 = __expf(trans[2 * TT + j]);
        float E3 = __expf(trans[3 * TT + j]);
        float eStart = __expf(trans[STARTS * TT + j]);
        float eStop  = __expf(trans[j * TT + STOPS]);

        float s = fshE[lane] * eStart;   // t = 0
        int eAcc = 0;

        for (int w = 0; w < 32; ++w) {
            #pragma unroll
            for (int k = 0; k < 16; ++k) {
                int t = w * 16 + k;
                if (t == 0) continue;
                float ef = fshE[t * 33 + lane];
                float s0 = __shfl_sync(0xffffffffu, s, qb + 0);
                float s1 = __shfl_sync(0xffffffffu, s, qb + 1);
                float s2 = __shfl_sync(0xffffffffu, s, qb + 2);
                float s3 = __shfl_sync(0xffffffffu, s, qb + 3);
                float u  = fmaf(s1, E1, s0 * E0);
                float v2 = fmaf(s3, E3, s2 * E2);
                s = (u + v2) * ef;
                if ((k & 7) == 0) {
                    // exact power-of-2 renorm every 8 steps; scale uniform
                    // across the quad (s0 is the shfl'd state-0 value)
                    int eb = (__float_as_int(s0) >> 23) & 0xff;
                    eAcc += eb - 127;
                    s *= __int_as_float((254 - eb) << 23);
                }
            }
        }

        // Z = log(sum_j s_j * e^{trStop_j}) + eAcc * ln2
        float zt = s * eStop;
        zt += __shfl_xor_sync(0xffffffffu, zt, 1);
        zt += __shfl_xor_sync(0xffffffffu, zt, 2);
        float Z = __logf(zt) + (float)eAcc * 0.69314718056f;
        if (j == 0) zsh[bb] = Z;
    } else if (warp == 1) {
        // ------------------- Viterbi (log domain) -------------------
        int bb = lane >> 2, j = lane & 3, qb = lane & ~3;
        float tr0 = trans[0 * TT + j];
        float tr1 = trans[1 * TT + j];
        float tr2 = trans[2 * TT + j];
        float tr3 = trans[3 * TT + j];
        float trStart = trans[STARTS * TT + j];
        float trStop  = trans[j * TT + STOPS];

        float delta = fshL[lane] + trStart;   // t = 0
        unsigned bpw = 0;

        for (int w = 0; w < 32; ++w) {
            #pragma unroll
            for (int k = 0; k < 16; ++k) {
                int t = w * 16 + k;
                if (t == 0) continue;
                float feat = fshL[t * 33 + lane];
                float d0 = __shfl_sync(0xffffffffu, delta, qb + 0);
                float d1 = __shfl_sync(0xffffffffu, delta, qb + 1);
                float d2 = __shfl_sync(0xffffffffu, delta, qb + 2);
                float d3 = __shfl_sync(0xffffffffu, delta, qb + 3);
                float v0 = d0 + tr0, v1 = d1 + tr1;
                float v2 = d2 + tr2, v3 = d3 + tr3;
                float m01 = fmaxf(v0, v1); int i01 = (v1 > v0) ? 1 : 0;
                float m23 = fmaxf(v2, v3); int i23 = (v3 > v2) ? 3 : 2;
                float best = fmaxf(m01, m23);
                int   bi2  = (m23 > m01) ? i23 : i01;
                delta = best + feat;
                bpw |= (unsigned)bi2 << (k * 2);
            }
            bp_s[w * 32 + lane] = bpw;
            bpw = 0;
        }

        // last_tag = argmax_j(delta + trStop) (first index on ties)
        float score = delta + trStop;
        int bi = j;
        #pragma unroll
        for (int off = 1; off < 4; off <<= 1) {
            float o = __shfl_xor_sync(0xffffffffu, score, off);
            int  oi = __shfl_xor_sync(0xffffffffu, bi, off);
            if (o > score || (o == score && oi < bi)) { score = o; bi = oi; }
        }
        __syncwarp();

        // Backtrace: 8 lanes (one per batch), one LDS.128 per 16 steps
        if (j == 0) {
            int batch = blockIdx.x * 8 + bb;
            int cur = bi;
            float* op = out + OUT_CRF_PRED + (size_t)batch * S;
            op[S - 1] = (float)cur;
            for (int w = 31; w >= 0; --w) {
                uint4 ws = *(const uint4*)&bp_s[w * 32 + bb * 4];
                #pragma unroll
                for (int k = 15; k >= 0; --k) {
                    int t = w * 16 + k;
                    if (t == 0) break;
                    unsigned word = (cur == 0) ? ws.x : (cur == 1) ? ws.y
                                  : (cur == 2) ? ws.z : ws.w;
                    cur = (word >> (2 * k)) & 3;
                    op[t - 1] = (float)cur;
                }
            }
        }
    } else {
        // ------------------- gold score + tags -------------------
        int bb2 = warp - 2;
        int b = blockIdx.x * 8 + bb2;
        const int* tg = asl + b * S1 + 1;   // tags[b][t] = asl[b][t+1]
        float acc = 0.f;
        for (int t = lane; t < S; t += 32) {
            int tag = tg[t];
            acc += fshL[t * 33 + bb2 * 4 + tag];
            out[OUT_TAGS + b * S + t] = (float)tag;
            if (t < S - 1) acc += trans[tag * TT + tg[t + 1]];
        }
        #pragma unroll
        for (int off = 16; off; off >>= 1)
            acc += __shfl_down_sync(0xffffffffu, acc, off);
        if (lane == 0)
            gsh[bb2] = acc + trans[STARTS * TT + tg[0]]
                           + trans[tg[S - 1] * TT + STOPS];
    }
    __syncthreads();

    // ------------------- epilogue: CLS head + losses -------------------
    if (tid < 8) {
        int b = blockIdx.x * 8 + tid;
        float crfc = zsh[tid] - gsh[tid];
        float l0 = g_isqa_logits[b * 2 + 0];
        float l1 = g_isqa_logits[b * 2 + 1];
        float m = fmaxf(l0, l1);
        float lse = m + __logf(__expf(l0 - m) + __expf(l1 - m));
        int y = isqa_in[b];
        float lossc = lse - (y ? l1 : l0);
        out[OUT_ISQA_PRED + b] = (l1 > l0) ? 1.f : 0.f;
        out[OUT_ISQA + b] = (float)y;
        #pragma unroll
        for (int off = 4; off; off >>= 1) {
            crfc  += __shfl_down_sync(0xffu, crfc,  off);
            lossc += __shfl_down_sync(0xffu, lossc, off);
        }
        if (tid == 0) {
            atomicAdd(&g_accCrf,  crfc);
            atomicAdd(&g_accIsqa, lossc);
            __threadfence();
            unsigned old = atomicAdd(&g_cnt, 1u);
            if (old == 7u) {
                __threadfence();
                out[OUT_CRF_LOSS]  = (*(volatile float*)&g_accCrf)  * (1.f / 64.f);
                out[OUT_ISQA_LOSS] = (*(volatile float*)&g_accIsqa) * (1.f / 64.f);
            }
        }
    }
}

// ---------------------------------------------------------------------------
extern "C" void kernel_launch(void* const* d_in, const int* in_sizes, int n_in,
                              void* d_out, int out_size)
{
    const float* emb   = (const float*)d_in[0];
    const int*   asl   = (const int*)  d_in[1];
    const int*   isqa  = (const int*)  d_in[2];
    const float* fc2W  = (const float*)d_in[3];
    const float* fc2b  = (const float*)d_in[4];
    const float* crfW  = (const float*)d_in[5];
    const float* crfb  = (const float*)d_in[6];
    const float* trans = (const float*)d_in[7];
    float* out = (float*)d_out;

    static bool attr_set = false;
    if (!attr_set) {
        cudaFuncSetAttribute(scanKernel,
                             cudaFuncAttributeMaxDynamicSharedMemorySize,
                             SCAN_SMEM);
        attr_set = true;
    }

    featsKernel<<<592, 256>>>(emb, fc2W, fc2b, crfW, crfb);
    scanKernel<<<8, 320, SCAN_SMEM>>>(trans, asl, isqa, out);
}

// round 9
// speedup vs baseline: 1.5289x; 1.2656x over previous
#include <cuda_runtime.h>
#include <cstdint>
#include <math.h>

#define H      768
#define TT     4
#define NB     64
#define S1     513
#define S      512
#define NBB    4          // batches per scan block

// Output layout (float32), reference tuple order:
// isqa_pred(64) | crf_pred(64*512) | isqa_loss(1) | crf_loss(1) | tags(64*512) | IsQA(64)
#define OUT_ISQA_PRED 0
#define OUT_CRF_PRED  64
#define OUT_ISQA_LOSS 32832
#define OUT_CRF_LOSS  32833
#define OUT_TAGS      32834
#define OUT_ISQA      65602

// Static device scratch (no allocation allowed)
__device__ float    g_feats[NB * S * TT];   // (b, t, state), float4 per (b,t)
__device__ float    g_isqa_logits[NB * 2];
__device__ float    g_accCrf, g_accIsqa;
__device__ unsigned g_cnt;

// ---------------------------------------------------------------------------
// Kernel A: feats[b][t][j] = emb[b][t+1] . crf_W[j] + crf_b[j]
//           isqa_logits[b][k] = emb[b][0] . fc2_W[k] + fc2_b[k]
// Warp per row; weights staged in shared once per block; float4 coalesced.
// Also resets the cross-kernel accumulators for this replay.
// ---------------------------------------------------------------------------
__global__ void __launch_bounds__(256) featsKernel(
    const float* __restrict__ emb,
    const float* __restrict__ fc2W, const float* __restrict__ fc2b,
    const float* __restrict__ crfW, const float* __restrict__ crfb)
{
    if (blockIdx.x == 0 && threadIdx.x == 0) {
        g_cnt = 0u; g_accCrf = 0.f; g_accIsqa = 0.f;
    }

    __shared__ float Wsh[8 * H];   // rows 0-3 crf_W, 4-5 fc2_W, 6-7 zero
    __shared__ float bsh[8];
    for (int i = threadIdx.x; i < 8 * H; i += 256) {
        int row = i / H, col = i - row * H;
        float v = 0.f;
        if (row < 4)      v = crfW[i];
        else if (row < 6) v = fc2W[(row - 4) * H + col];
        Wsh[i] = v;
    }
    if (threadIdx.x < 8) {
        int r = threadIdx.x;
        bsh[r] = (r < 4) ? crfb[r] : ((r < 6) ? fc2b[r - 4] : 0.f);
    }
    __syncthreads();

    int warp = threadIdx.x >> 5, lane = threadIdx.x & 31;
    int nwarps = gridDim.x * 8;
    for (int r = blockIdx.x * 8 + warp; r < NB * S1; r += nwarps) {
        int b = r / S1, s = r - b * S1;
        const float4* e4 = (const float4*)(emb + (size_t)r * H);
        int wbase = (s == 0) ? 4 : 0;
        const float4* w0 = (const float4*)(Wsh + (wbase + 0) * H);
        const float4* w1 = (const float4*)(Wsh + (wbase + 1) * H);
        const float4* w2 = (const float4*)(Wsh + (wbase + 2) * H);
        const float4* w3 = (const float4*)(Wsh + (wbase + 3) * H);
        float p0 = 0.f, p1 = 0.f, p2 = 0.f, p3 = 0.f;
        #pragma unroll
        for (int i = 0; i < 6; i++) {
            int idx = lane + 32 * i;
            float4 v = e4[idx];
            float4 a = w0[idx];
            p0 += v.x * a.x + v.y * a.y + v.z * a.z + v.w * a.w;
            float4 c = w1[idx];
            p1 += v.x * c.x + v.y * c.y + v.z * c.z + v.w * c.w;
            float4 d = w2[idx];
            p2 += v.x * d.x + v.y * d.y + v.z * d.z + v.w * d.w;
            float4 e = w3[idx];
            p3 += v.x * e.x + v.y * e.y + v.z * e.z + v.w * e.w;
        }
        #pragma unroll
        for (int off = 16; off; off >>= 1) {
            p0 += __shfl_xor_sync(0xffffffffu, p0, off);
            p1 += __shfl_xor_sync(0xffffffffu, p1, off);
            p2 += __shfl_xor_sync(0xffffffffu, p2, off);
            p3 += __shfl_xor_sync(0xffffffffu, p3, off);
        }
        if (lane == 0) {
            if (s == 0) {
                g_isqa_logits[b * 2 + 0] = p0 + bsh[4];
                g_isqa_logits[b * 2 + 1] = p1 + bsh[5];
            } else {
                float4 o = make_float4(p0 + bsh[0], p1 + bsh[1],
                                       p2 + bsh[2], p3 + bsh[3]);
                ((float4*)g_feats)[b * S + (s - 1)] = o;
            }
        }
    }
}

// ---------------------------------------------------------------------------
// Kernel B: 32 blocks x 256 threads, 4 batches per block.
//   blocks 0-15  (viterbi role): sequential Viterbi (per-thread, all 4 states
//       in registers, delta stored to smem every step) + gold score + tags,
//       then parallel backpointer recompute from stored deltas, then
//       backtrace + coalesced pred writeout + gold accumulation.
//   blocks 16-31 (forward role): linear-domain log-partition (per-thread,
//       power-of-2 renorm) -> Z, plus CLS/isqa head + loss accumulation.
// No shuffles anywhere on the 511-step recurrences.
// ---------------------------------------------------------------------------
// Dynamic smem (viterbi role):
//   FL   : float4[512*4]   feats (log)        32KB   offset 0
//   DD   : float4[512*4]   delta per step     32KB   offset 2048 (f4)
//   BP   : uint4 [32*4]    packed backptrs     2KB   offset 4096 (f4)
//   PRED : float [4*512]   decoded path        8KB   offset 4224 (f4)
// Forward role uses only the first 32KB (exp feats).
#define SCAN_SMEM ((4224 + 512) * 16)

__global__ void __launch_bounds__(256) scanKernel(
    const float* __restrict__ trans,
    const int*   __restrict__ asl,
    const int*   __restrict__ isqa_in,
    float* __restrict__ out)
{
    extern __shared__ float4 sm4[];
    float4* FL    = sm4;                 // log feats (viterbi) / exp feats (fwd)
    float4* DD    = sm4 + 2048;
    uint4*  BP    = (uint4*)(sm4 + 4096);
    float4* PRED4 = sm4 + 4224;
    float*  PRED  = (float*)PRED4;
    __shared__ float aux[8];

    int tid  = threadIdx.x;
    int warp = tid >> 5, lane = tid & 31;
    bool isFwd = blockIdx.x >= 16;
    int bb0 = (blockIdx.x & 15) * NBB;
    const float4* gf = (const float4*)g_feats + (size_t)bb0 * S;

    // ---------------- staging ----------------
    if (!isFwd) {
        for (int v = tid; v < NBB * S; v += 256) {
            int bbv = v >> 9, t = v & 511;
            FL[t * NBB + bbv] = gf[bbv * S + t];
        }
    } else {
        for (int v = tid; v < NBB * S; v += 256) {
            int bbv = v >> 9, t = v & 511;
            float4 f = gf[bbv * S + t];
            FL[t * NBB + bbv] = make_float4(__expf(f.x), __expf(f.y),
                                            __expf(f.z), __expf(f.w));
        }
    }
    __syncthreads();

    if (!isFwd) {
        // ============== VITERBI ROLE ==============
        if (warp == 0 && lane < NBB) {
            // sequential max-plus recurrence, one thread = one batch
            int bb = lane;
            float t00 = trans[0],  t01 = trans[1],  t02 = trans[2],  t03 = trans[3];
            float t10 = trans[4],  t11 = trans[5],  t12 = trans[6],  t13 = trans[7];
            float t20 = trans[8],  t21 = trans[9],  t22 = trans[10], t23 = trans[11];
            float t30 = trans[12], t31 = trans[13], t32 = trans[14], t33 = trans[15];
            float4 f0 = FL[bb];
            float d0 = f0.x + t20, d1 = f0.y + t21;   // START row = 2
            float d2 = f0.z + t22, d3 = f0.w + t23;
            DD[bb] = make_float4(d0, d1, d2, d3);
            #pragma unroll 8
            for (int t = 1; t < S; ++t) {
                float4 f = FL[t * NBB + bb];
                float n0 = fmaxf(fmaxf(d0 + t00, d1 + t10),
                                 fmaxf(d2 + t20, d3 + t30)) + f.x;
                float n1 = fmaxf(fmaxf(d0 + t01, d1 + t11),
                                 fmaxf(d2 + t21, d3 + t31)) + f.y;
                float n2 = fmaxf(fmaxf(d0 + t02, d1 + t12),
                                 fmaxf(d2 + t22, d3 + t32)) + f.z;
                float n3 = fmaxf(fmaxf(d0 + t03, d1 + t13),
                                 fmaxf(d2 + t23, d3 + t33)) + f.w;
                d0 = n0; d1 = n1; d2 = n2; d3 = n3;
                DD[t * NBB + bb] = make_float4(d0, d1, d2, d3);
            }
        } else if (warp >= 1 && warp <= NBB) {
            // gold score + tags for batch (warp-1), concurrent with seq warp
            int bb = warp - 1, b = bb0 + bb;
            const int* tg = asl + b * S1 + 1;
            float acc = 0.f;
            for (int t = lane; t < S; t += 32) {
                int tag = tg[t];
                acc += ((const float*)&FL[t * NBB + bb])[tag];
                out[OUT_TAGS + b * S + t] = (float)tag;
                if (t < S - 1) acc += trans[tag * TT + tg[t + 1]];
            }
            #pragma unroll
            for (int off = 16; off; off >>= 1)
                acc += __shfl_down_sync(0xffffffffu, acc, off);
            if (lane == 0)
                aux[bb] = acc + trans[2 * TT + tg[0]]
                              + trans[tg[S - 1] * TT + 3];
        }
        __syncthreads();

        // ---- parallel backpointer recompute from stored deltas ----
        if (tid < 128) {
            int w = tid >> 2, bb = tid & 3;
            float t00 = trans[0],  t01 = trans[1],  t02 = trans[2],  t03 = trans[3];
            float t10 = trans[4],  t11 = trans[5],  t12 = trans[6],  t13 = trans[7];
            float t20 = trans[8],  t21 = trans[9],  t22 = trans[10], t23 = trans[11];
            float t30 = trans[12], t31 = trans[13], t32 = trans[14], t33 = trans[15];
            unsigned r0 = 0, r1 = 0, r2 = 0, r3 = 0;
            #pragma unroll
            for (int k = 0; k < 16; ++k) {
                int t = w * 16 + k;
                if (t == 0) continue;
                float4 d = DD[(t - 1) * NBB + bb];
                // j = 0
                {
                    float v0 = d.x + t00, v1 = d.y + t10, v2 = d.z + t20, v3 = d.w + t30;
                    float best = v0; int bi = 0;
                    if (v1 > best) { best = v1; bi = 1; }
                    if (v2 > best) { best = v2; bi = 2; }
                    if (v3 > best) { best = v3; bi = 3; }
                    r0 |= (unsigned)bi << (2 * k);
                }
                // j = 1
                {
                    float v0 = d.x + t01, v1 = d.y + t11, v2 = d.z + t21, v3 = d.w + t31;
                    float best = v0; int bi = 0;
                    if (v1 > best) { best = v1; bi = 1; }
                    if (v2 > best) { best = v2; bi = 2; }
                    if (v3 > best) { best = v3; bi = 3; }
                    r1 |= (unsigned)bi << (2 * k);
                }
                // j = 2
                {
                    float v0 = d.x + t02, v1 = d.y + t12, v2 = d.z + t22, v3 = d.w + t32;
                    float best = v0; int bi = 0;
                    if (v1 > best) { best = v1; bi = 1; }
                    if (v2 > best) { best = v2; bi = 2; }
                    if (v3 > best) { best = v3; bi = 3; }
                    r2 |= (unsigned)bi << (2 * k);
                }
                // j = 3
                {
                    float v0 = d.x + t03, v1 = d.y + t13, v2 = d.z + t23, v3 = d.w + t33;
                    float best = v0; int bi = 0;
                    if (v1 > best) { best = v1; bi = 1; }
                    if (v2 > best) { best = v2; bi = 2; }
                    if (v3 > best) { best = v3; bi = 3; }
                    r3 |= (unsigned)bi << (2 * k);
                }
            }
            BP[w * 4 + bb] = make_uint4(r0, r1, r2, r3);
        }
        __syncthreads();

        // ---- backtrace (one thread per batch) ----
        if (tid < NBB) {
            int bb = tid;
            float4 dl = DD[(S - 1) * NBB + bb];
            float s0 = dl.x + trans[3],  s1 = dl.y + trans[7];
            float s2 = dl.z + trans[11], s3 = dl.w + trans[15];
            float best = s0; int cur = 0;
            if (s1 > best) { best = s1; cur = 1; }
            if (s2 > best) { best = s2; cur = 2; }
            if (s3 > best) { best = s3; cur = 3; }
            PRED[bb * S + S - 1] = (float)cur;
            for (int w = 31; w >= 0; --w) {
                uint4 ws = BP[w * 4 + bb];
                #pragma unroll
                for (int k = 15; k >= 0; --k) {
                    int t = w * 16 + k;
                    if (t == 0) break;
                    unsigned word = (cur == 0) ? ws.x : (cur == 1) ? ws.y
                                  : (cur == 2) ? ws.z : ws.w;
                    cur = (word >> (2 * k)) & 3;
                    PRED[bb * S + t - 1] = (float)cur;
                }
            }
        }
        __syncthreads();

        // ---- coalesced pred writeout ----
        for (int v = tid; v < NBB * (S / 4); v += 256) {
            int bbv = v >> 7, idx = v & 127;
            ((float4*)(out + OUT_CRF_PRED + (size_t)(bb0 + bbv) * S))[idx]
                = PRED4[bbv * (S / 4) + idx];
        }

        // ---- gold accumulation + finalize ----
        if (tid == 0) {
            float gsum = aux[0] + aux[1] + aux[2] + aux[3];
            atomicAdd(&g_accCrf, -gsum);
            __threadfence();
            unsigned old = atomicAdd(&g_cnt, 1u);
            if (old == 31u) {
                __threadfence();
                out[OUT_CRF_LOSS]  = (*(volatile float*)&g_accCrf)  * (1.f / 64.f);
                out[OUT_ISQA_LOSS] = (*(volatile float*)&g_accIsqa) * (1.f / 64.f);
            }
        }
    } else {
        // ============== FORWARD ROLE ==============
        if (warp == 0 && lane < NBB) {
            int bb = lane;
            float E00 = __expf(trans[0]),  E01 = __expf(trans[1]);
            float E02 = __expf(trans[2]),  E03 = __expf(trans[3]);
            float E10 = __expf(trans[4]),  E11 = __expf(trans[5]);
            float E12 = __expf(trans[6]),  E13 = __expf(trans[7]);
            float E20 = __expf(trans[8]),  E21 = __expf(trans[9]);
            float E22 = __expf(trans[10]), E23 = __expf(trans[11]);
            float E30 = __expf(trans[12]), E31 = __expf(trans[13]);
            float E32 = __expf(trans[14]), E33 = __expf(trans[15]);
            float P0 = __expf(trans[3]),  P1 = __expf(trans[7]);
            float P2 = __expf(trans[11]), P3 = __expf(trans[15]);

            float4 f0 = FL[bb];
            float s0 = f0.x * E20, s1 = f0.y * E21;   // START row = 2
            float s2 = f0.z * E22, s3 = f0.w * E23;
            int eAcc = 0;

            // 63 chunks of 8 steps (t = 1..504) with renorm, then tail 505..511
            int t = 1;
            for (int w = 0; w < 63; ++w) {
                #pragma unroll
                for (int k = 0; k < 8; ++k, ++t) {
                    float4 ef = FL[t * NBB + bb];
                    float n0 = fmaf(s3, E30, fmaf(s2, E20, fmaf(s1, E10, s0 * E00))) * ef.x;
                    float n1 = fmaf(s3, E31, fmaf(s2, E21, fmaf(s1, E11, s0 * E01))) * ef.y;
                    float n2 = fmaf(s3, E32, fmaf(s2, E22, fmaf(s1, E12, s0 * E02))) * ef.z;
                    float n3 = fmaf(s3, E33, fmaf(s2, E23, fmaf(s1, E13, s0 * E03))) * ef.w;
                    s0 = n0; s1 = n1; s2 = n2; s3 = n3;
                }
                // exact power-of-2 renorm (s all > 0)
                int e = (__float_as_int(s0) >> 23) & 255;
                eAcc += e - 127;
                float sc = __int_as_float((unsigned)(254 - e) << 23);
                s0 *= sc; s1 *= sc; s2 *= sc; s3 *= sc;
            }
            #pragma unroll
            for (int k = 0; k < 7; ++k, ++t) {
                float4 ef = FL[t * NBB + bb];
                float n0 = fmaf(s3, E30, fmaf(s2, E20, fmaf(s1, E10, s0 * E00))) * ef.x;
                float n1 = fmaf(s3, E31, fmaf(s2, E21, fmaf(s1, E11, s0 * E01))) * ef.y;
                float n2 = fmaf(s3, E32, fmaf(s2, E22, fmaf(s1, E12, s0 * E02))) * ef.z;
                float n3 = fmaf(s3, E33, fmaf(s2, E23, fmaf(s1, E13, s0 * E03))) * ef.w;
                s0 = n0; s1 = n1; s2 = n2; s3 = n3;
            }

            float zt = (s0 * P0 + s1 * P1) + (s2 * P2 + s3 * P3);
            float Z = __logf(zt) + (float)eAcc * 0.693147180559945f;
            aux[bb] = Z;

            // CLS / isqa head for this batch
            int b = bb0 + bb;
            float l0 = g_isqa_logits[b * 2 + 0];
            float l1 = g_isqa_logits[b * 2 + 1];
            float m = fmaxf(l0, l1);
            float lse = m + __logf(__expf(l0 - m) + __expf(l1 - m));
            int y = isqa_in[b];
            aux[4 + bb] = lse - (y ? l1 : l0);
            out[OUT_ISQA_PRED + b] = (l1 > l0) ? 1.f : 0.f;
            out[OUT_ISQA + b] = (float)y;

            __syncwarp(0xFu);
            if (lane == 0) {
                atomicAdd(&g_accCrf,  aux[0] + aux[1] + aux[2] + aux[3]);
                atomicAdd(&g_accIsqa, aux[4] + aux[5] + aux[6] + aux[7]);
                __threadfence();
                unsigned old = atomicAdd(&g_cnt, 1u);
                if (old == 31u) {
                    __threadfence();
                    out[OUT_CRF_LOSS]  = (*(volatile float*)&g_accCrf)  * (1.f / 64.f);
                    out[OUT_ISQA_LOSS] = (*(volatile float*)&g_accIsqa) * (1.f / 64.f);
                }
            }
        }
    }
}

// ---------------------------------------------------------------------------
extern "C" void kernel_launch(void* const* d_in, const int* in_sizes, int n_in,
                              void* d_out, int out_size)
{
    const float* emb   = (const float*)d_in[0];
    const int*   asl   = (const int*)  d_in[1];
    const int*   isqa  = (const int*)  d_in[2];
    const float* fc2W  = (const float*)d_in[3];
    const float* fc2b  = (const float*)d_in[4];
    const float* crfW  = (const float*)d_in[5];
    const float* crfb  = (const float*)d_in[6];
    const float* trans = (const float*)d_in[7];
    float* out = (float*)d_out;

    cudaFuncSetAttribute(scanKernel,
                         cudaFuncAttributeMaxDynamicSharedMemorySize,
                         SCAN_SMEM);

    featsKernel<<<592, 256>>>(emb, fc2W, fc2b, crfW, crfb);
    scanKernel<<<32, 256, SCAN_SMEM>>>(trans, asl, isqa, out);
}

// round 11
// speedup vs baseline: 2.3072x; 1.5091x over previous
#include <cuda_runtime.h>
#include <cstdint>
#include <math.h>

#define H      768
#define TT     4
#define NB     64
#define S1     513
#define S      512
#define NBB    4          // batches per scan block

// Output layout (float32), reference tuple order:
// isqa_pred(64) | crf_pred(64*512) | isqa_loss(1) | crf_loss(1) | tags(64*512) | IsQA(64)
#define OUT_ISQA_PRED 0
#define OUT_CRF_PRED  64
#define OUT_ISQA_LOSS 32832
#define OUT_CRF_LOSS  32833
#define OUT_TAGS      32834
#define OUT_ISQA      65602

// Static device scratch (no allocation allowed)
__device__ float    g_feats[NB * S * TT];   // (b, t, state), float4 per (b,t)
__device__ float    g_isqa_logits[NB * 2];
__device__ float    g_accCrf, g_accIsqa;
__device__ unsigned g_cnt;

// ---------------------------------------------------------------------------
// Kernel A: feats[b][t][j] = emb[b][t+1] . crf_W[j] + crf_b[j]
//           isqa_logits[b][k] = emb[b][0] . fc2_W[k] + fc2_b[k]
// ---------------------------------------------------------------------------
__global__ void __launch_bounds__(256) featsKernel(
    const float* __restrict__ emb,
    const float* __restrict__ fc2W, const float* __restrict__ fc2b,
    const float* __restrict__ crfW, const float* __restrict__ crfb)
{
    if (blockIdx.x == 0 && threadIdx.x == 0) {
        g_cnt = 0u; g_accCrf = 0.f; g_accIsqa = 0.f;
    }

    __shared__ float Wsh[8 * H];   // rows 0-3 crf_W, 4-5 fc2_W, 6-7 zero
    __shared__ float bsh[8];
    for (int i = threadIdx.x; i < 8 * H; i += 256) {
        int row = i / H, col = i - row * H;
        float v = 0.f;
        if (row < 4)      v = crfW[i];
        else if (row < 6) v = fc2W[(row - 4) * H + col];
        Wsh[i] = v;
    }
    if (threadIdx.x < 8) {
        int r = threadIdx.x;
        bsh[r] = (r < 4) ? crfb[r] : ((r < 6) ? fc2b[r - 4] : 0.f);
    }
    __syncthreads();

    int warp = threadIdx.x >> 5, lane = threadIdx.x & 31;
    int nwarps = gridDim.x * 8;
    for (int r = blockIdx.x * 8 + warp; r < NB * S1; r += nwarps) {
        int b = r / S1, s = r - b * S1;
        const float4* e4 = (const float4*)(emb + (size_t)r * H);
        int wbase = (s == 0) ? 4 : 0;
        const float4* w0 = (const float4*)(Wsh + (wbase + 0) * H);
        const float4* w1 = (const float4*)(Wsh + (wbase + 1) * H);
        const float4* w2 = (const float4*)(Wsh + (wbase + 2) * H);
        const float4* w3 = (const float4*)(Wsh + (wbase + 3) * H);
        float p0 = 0.f, p1 = 0.f, p2 = 0.f, p3 = 0.f;
        #pragma unroll
        for (int i = 0; i < 6; i++) {
            int idx = lane + 32 * i;
            float4 v = e4[idx];
            float4 a = w0[idx];
            p0 += v.x * a.x + v.y * a.y + v.z * a.z + v.w * a.w;
            float4 c = w1[idx];
            p1 += v.x * c.x + v.y * c.y + v.z * c.z + v.w * c.w;
            float4 d = w2[idx];
            p2 += v.x * d.x + v.y * d.y + v.z * d.z + v.w * d.w;
            float4 e = w3[idx];
            p3 += v.x * e.x + v.y * e.y + v.z * e.z + v.w * e.w;
        }
        #pragma unroll
        for (int off = 16; off; off >>= 1) {
            p0 += __shfl_xor_sync(0xffffffffu, p0, off);
            p1 += __shfl_xor_sync(0xffffffffu, p1, off);
            p2 += __shfl_xor_sync(0xffffffffu, p2, off);
            p3 += __shfl_xor_sync(0xffffffffu, p3, off);
        }
        if (lane == 0) {
            if (s == 0) {
                g_isqa_logits[b * 2 + 0] = p0 + bsh[4];
                g_isqa_logits[b * 2 + 1] = p1 + bsh[5];
            } else {
                float4 o = make_float4(p0 + bsh[0], p1 + bsh[1],
                                       p2 + bsh[2], p3 + bsh[3]);
                ((float4*)g_feats)[b * S + (s - 1)] = o;
            }
        }
    }
}

// ---------------------------------------------------------------------------
// Kernel B: 32 blocks x 256 threads, 4 batches per block.
//   blocks 0-15  (viterbi role): sequential Viterbi (per-thread, 4 states in
//     regs, delta stored every step), gold+tags concurrent, then parallel
//     backpointer recompute + CHUNK-PARALLEL backtrace, coalesced writeout.
//   blocks 16-31 (forward role): linear-domain log-partition (per-thread,
//     power-of-2 renorm) -> Z, plus CLS/isqa head + loss accumulation.
// __launch_bounds__(256,1): give ptxas a full register budget so the 16
// loop-invariant transition values stay resident (no rematerialization).
// ---------------------------------------------------------------------------
#define SCAN_SMEM ((4096 + 512) * 16)   // FL 32KB + DD 32KB + PRED 8KB

__global__ void __launch_bounds__(256, 1) scanKernel(
    const float* __restrict__ trans,
    const int*   __restrict__ asl,
    const int*   __restrict__ isqa_in,
    float* __restrict__ out)
{
    extern __shared__ float4 sm4[];
    float4* FL    = sm4;                 // log feats (viterbi) / exp feats (fwd)
    float4* DD    = sm4 + 2048;
    float4* PRED4 = sm4 + 4096;
    float*  PRED  = (float*)PRED4;
    __shared__ float    aux[8];
    __shared__ unsigned PATHS[NBB * 32 * 4];   // [bb][chunk][entry] packed path
    __shared__ int      ESEL[NBB * 32];        // chosen entry per chunk
    __shared__ int      LT[NBB];               // last tag per batch

    int tid  = threadIdx.x;
    int warp = tid >> 5, lane = tid & 31;
    bool isFwd = blockIdx.x >= 16;
    int bb0 = (blockIdx.x & 15) * NBB;
    const float4* gf = (const float4*)g_feats + (size_t)bb0 * S;

    // ---------------- staging ----------------
    if (!isFwd) {
        for (int v = tid; v < NBB * S; v += 256) {
            int bbv = v >> 9, t = v & 511;
            FL[t * NBB + bbv] = gf[bbv * S + t];
        }
    } else {
        for (int v = tid; v < NBB * S; v += 256) {
            int bbv = v >> 9, t = v & 511;
            float4 f = gf[bbv * S + t];
            FL[t * NBB + bbv] = make_float4(__expf(f.x), __expf(f.y),
                                            __expf(f.z), __expf(f.w));
        }
    }
    __syncthreads();

    if (!isFwd) {
        // ============== VITERBI ROLE ==============
        if (warp == 0 && lane < NBB) {
            // sequential max-plus recurrence, one thread = one batch
            int bb = lane;
            float t00 = trans[0],  t01 = trans[1],  t02 = trans[2],  t03 = trans[3];
            float t10 = trans[4],  t11 = trans[5],  t12 = trans[6],  t13 = trans[7];
            float t20 = trans[8],  t21 = trans[9],  t22 = trans[10], t23 = trans[11];
            float t30 = trans[12], t31 = trans[13], t32 = trans[14], t33 = trans[15];
            float4 f0 = FL[bb];
            float d0 = f0.x + t20, d1 = f0.y + t21;   // START row = 2
            float d2 = f0.z + t22, d3 = f0.w + t23;
            DD[bb] = make_float4(d0, d1, d2, d3);
            float4 fc = FL[NBB + bb];                  // prefetch t=1
#define VSTEP(FV, T)                                                         \
            {                                                                \
                float n0 = fmaxf(fmaxf(d0 + t00, d1 + t10),                  \
                                 fmaxf(d2 + t20, d3 + t30)) + (FV).x;        \
                float n1 = fmaxf(fmaxf(d0 + t01, d1 + t11),                  \
                                 fmaxf(d2 + t21, d3 + t31)) + (FV).y;        \
                float n2 = fmaxf(fmaxf(d0 + t02, d1 + t12),                  \
                                 fmaxf(d2 + t22, d3 + t32)) + (FV).z;        \
                float n3 = fmaxf(fmaxf(d0 + t03, d1 + t13),                  \
                                 fmaxf(d2 + t23, d3 + t33)) + (FV).w;        \
                d0 = n0; d1 = n1; d2 = n2; d3 = n3;                          \
                DD[(T) * NBB + bb] = make_float4(d0, d1, d2, d3);            \
            }
            #pragma unroll 8
            for (int t = 1; t < S - 1; ++t) {
                float4 f = fc;
                fc = FL[(t + 1) * NBB + bb];
                VSTEP(f, t);
            }
            VSTEP(fc, S - 1);
#undef VSTEP
        } else if (warp >= 1 && warp <= NBB) {
            // gold score + tags for batch (warp-1), concurrent with seq warp
            int bb = warp - 1, b = bb0 + bb;
            const int* tg = asl + b * S1 + 1;
            float acc = 0.f;
            for (int t = lane; t < S; t += 32) {
                int tag = tg[t];
                acc += ((const float*)&FL[t * NBB + bb])[tag];
                out[OUT_TAGS + b * S + t] = (float)tag;
                if (t < S - 1) acc += trans[tag * TT + tg[t + 1]];
            }
            #pragma unroll
            for (int off = 16; off; off >>= 1)
                acc += __shfl_down_sync(0xffffffffu, acc, off);
            if (lane == 0)
                aux[bb] = acc + trans[2 * TT + tg[0]]
                              + trans[tg[S - 1] * TT + 3];
        }
        __syncthreads();

        // ---- parallel backpointer recompute + per-chunk path decode ----
        // thread (w, bb): recompute 16 steps of backpointers from stored
        // deltas into registers r0..r3 (one word per destination state),
        // then walk each of the 4 possible entry states through the chunk.
        if (tid < 128) {
            int w = tid >> 2, bb = tid & 3;
            float t00 = trans[0],  t01 = trans[1],  t02 = trans[2],  t03 = trans[3];
            float t10 = trans[4],  t11 = trans[5],  t12 = trans[6],  t13 = trans[7];
            float t20 = trans[8],  t21 = trans[9],  t22 = trans[10], t23 = trans[11];
            float t30 = trans[12], t31 = trans[13], t32 = trans[14], t33 = trans[15];
            unsigned r0 = 0, r1 = 0, r2 = 0, r3 = 0;
            #pragma unroll
            for (int k = 0; k < 16; ++k) {
                int t = w * 16 + k;
                if (t == 0) continue;
                float4 d = DD[(t - 1) * NBB + bb];
                {
                    float v0 = d.x + t00, v1 = d.y + t10, v2 = d.z + t20, v3 = d.w + t30;
                    float best = v0; int bi = 0;
                    if (v1 > best) { best = v1; bi = 1; }
                    if (v2 > best) { best = v2; bi = 2; }
                    if (v3 > best) { best = v3; bi = 3; }
                    r0 |= (unsigned)bi << (2 * k);
                }
                {
                    float v0 = d.x + t01, v1 = d.y + t11, v2 = d.z + t21, v3 = d.w + t31;
                    float best = v0; int bi = 0;
                    if (v1 > best) { best = v1; bi = 1; }
                    if (v2 > best) { best = v2; bi = 2; }
                    if (v3 > best) { best = v3; bi = 3; }
                    r1 |= (unsigned)bi << (2 * k);
                }
                {
                    float v0 = d.x + t02, v1 = d.y + t12, v2 = d.z + t22, v3 = d.w + t32;
                    float best = v0; int bi = 0;
                    if (v1 > best) { best = v1; bi = 1; }
                    if (v2 > best) { best = v2; bi = 2; }
                    if (v3 > best) { best = v3; bi = 3; }
                    r2 |= (unsigned)bi << (2 * k);
                }
                {
                    float v0 = d.x + t03, v1 = d.y + t13, v2 = d.z + t23, v3 = d.w + t33;
                    float best = v0; int bi = 0;
                    if (v1 > best) { best = v1; bi = 1; }
                    if (v2 > best) { best = v2; bi = 2; }
                    if (v3 > best) { best = v3; bi = 3; }
                    r3 |= (unsigned)bi << (2 * k);
                }
            }
            // decode all 4 possible entry states through this chunk
            #pragma unroll
            for (int e = 0; e < 4; ++e) {
                int cur = e; unsigned path = 0;
                #pragma unroll
                for (int k = 15; k >= 0; --k) {
                    unsigned word = (cur == 0) ? r0 : (cur == 1) ? r1
                                  : (cur == 2) ? r2 : r3;
                    cur = (int)((word >> (2 * k)) & 3u);
                    path |= (unsigned)cur << (2 * k);
                }
                PATHS[(bb * 32 + w) * 4 + e] = path;
            }
        }
        __syncthreads();

        // ---- chunk-chain: pick entry state per chunk (one thread/batch) ----
        if (tid < NBB) {
            int bb = tid;
            float4 dl = DD[(S - 1) * NBB + bb];
            float s0 = dl.x + trans[3],  s1 = dl.y + trans[7];
            float s2 = dl.z + trans[11], s3 = dl.w + trans[15];
            float best = s0; int cur = 0;
            if (s1 > best) { best = s1; cur = 1; }
            if (s2 > best) { best = s2; cur = 2; }
            if (s3 > best) { best = s3; cur = 3; }
            LT[bb] = cur;
            PRED[bb * S + S - 1] = (float)cur;
            for (int w = 31; w >= 0; --w) {
                ESEL[bb * 32 + w] = cur;
                cur = (int)(PATHS[(bb * 32 + w) * 4 + cur] & 3u);
            }
        }
        __syncthreads();

        // ---- parallel path writeout into PRED smem ----
        if (tid < 128) {
            int w = tid >> 2, bb = tid & 3;
            int e = ESEL[bb * 32 + w];
            unsigned path = PATHS[(bb * 32 + w) * 4 + e];
            #pragma unroll
            for (int k = 15; k >= 0; --k) {
                int t = w * 16 + k;
                if (t == 0) continue;
                PRED[bb * S + t - 1] = (float)((path >> (2 * k)) & 3u);
            }
        }
        __syncthreads();

        // ---- coalesced pred writeout ----
        for (int v = tid; v < NBB * (S / 4); v += 256) {
            int bbv = v >> 7, idx = v & 127;
            ((float4*)(out + OUT_CRF_PRED + (size_t)(bb0 + bbv) * S))[idx]
                = PRED4[bbv * (S / 4) + idx];
        }

        // ---- gold accumulation + finalize ----
        if (tid == 0) {
            float gsum = aux[0] + aux[1] + aux[2] + aux[3];
            atomicAdd(&g_accCrf, -gsum);
            __threadfence();
            unsigned old = atomicAdd(&g_cnt, 1u);
            if (old == 31u) {
                __threadfence();
                out[OUT_CRF_LOSS]  = (*(volatile float*)&g_accCrf)  * (1.f / 64.f);
                out[OUT_ISQA_LOSS] = (*(volatile float*)&g_accIsqa) * (1.f / 64.f);
            }
        }
    } else {
        // ============== FORWARD ROLE ==============
        if (warp == 0 && lane < NBB) {
            int bb = lane;
            float E00 = __expf(trans[0]),  E01 = __expf(trans[1]);
            float E02 = __expf(trans[2]),  E03 = __expf(trans[3]);
            float E10 = __expf(trans[4]),  E11 = __expf(trans[5]);
            float E12 = __expf(trans[6]),  E13 = __expf(trans[7]);
            float E20 = __expf(trans[8]),  E21 = __expf(trans[9]);
            float E22 = __expf(trans[10]), E23 = __expf(trans[11]);
            float E30 = __expf(trans[12]), E31 = __expf(trans[13]);
            float E32 = __expf(trans[14]), E33 = __expf(trans[15]);
            float P0 = __expf(trans[3]),  P1 = __expf(trans[7]);
            float P2 = __expf(trans[11]), P3 = __expf(trans[15]);

            float4 f0 = FL[bb];
            float s0 = f0.x * E20, s1 = f0.y * E21;   // START row = 2
            float s2 = f0.z * E22, s3 = f0.w * E23;
            int eAcc = 0;
#define FSTEP(EF)                                                            \
            {                                                                \
                float n0 = fmaf(s3, E30, fmaf(s2, E20, fmaf(s1, E10, s0 * E00))) * (EF).x; \
                float n1 = fmaf(s3, E31, fmaf(s2, E21, fmaf(s1, E11, s0 * E01))) * (EF).y; \
                float n2 = fmaf(s3, E32, fmaf(s2, E22, fmaf(s1, E12, s0 * E02))) * (EF).z; \
                float n3 = fmaf(s3, E33, fmaf(s2, E23, fmaf(s1, E13, s0 * E03))) * (EF).w; \
                s0 = n0; s1 = n1; s2 = n2; s3 = n3;                          \
            }
            int t = 1;
            float4 fc = FL[NBB + bb];                  // prefetch t=1
            for (int w = 0; w < 63; ++w) {
                #pragma unroll
                for (int k = 0; k < 8; ++k, ++t) {
                    float4 ef = fc;
                    fc = FL[(t + 1) * NBB + bb];
                    FSTEP(ef);
                }
                // exact power-of-2 renorm (s all > 0)
                int e = (__float_as_int(s0) >> 23) & 255;
                eAcc += e - 127;
                float sc = __int_as_float((unsigned)(254 - e) << 23);
                s0 *= sc; s1 *= sc; s2 *= sc; s3 *= sc;
            }
            #pragma unroll
            for (int k = 0; k < 7; ++k, ++t) {         // t = 505..511
                float4 ef = fc;
                if (t < S - 1) fc = FL[(t + 1) * NBB + bb];
                FSTEP(ef);
            }
#undef FSTEP
            float zt = (s0 * P0 + s1 * P1) + (s2 * P2 + s3 * P3);
            float Z = __logf(zt) + (float)eAcc * 0.693147180559945f;
            aux[bb] = Z;

            // CLS / isqa head for this batch
            int b = bb0 + bb;
            float l0 = g_isqa_logits[b * 2 + 0];
            float l1 = g_isqa_logits[b * 2 + 1];
            float m = fmaxf(l0, l1);
            float lse = m + __logf(__expf(l0 - m) + __expf(l1 - m));
            int y = isqa_in[b];
            aux[4 + bb] = lse - (y ? l1 : l0);
            out[OUT_ISQA_PRED + b] = (l1 > l0) ? 1.f : 0.f;
            out[OUT_ISQA + b] = (float)y;

            __syncwarp(0xFu);
            if (lane == 0) {
                atomicAdd(&g_accCrf,  aux[0] + aux[1] + aux[2] + aux[3]);
                atomicAdd(&g_accIsqa, aux[4] + aux[5] + aux[6] + aux[7]);
                __threadfence();
                unsigned old = atomicAdd(&g_cnt, 1u);
                if (old == 31u) {
                    __threadfence();
                    out[OUT_CRF_LOSS]  = (*(volatile float*)&g_accCrf)  * (1.f / 64.f);
                    out[OUT_ISQA_LOSS] = (*(volatile float*)&g_accIsqa) * (1.f / 64.f);
                }
            }
        }
    }
}

// ---------------------------------------------------------------------------
extern "C" void kernel_launch(void* const* d_in, const int* in_sizes, int n_in,
                              void* d_out, int out_size)
{
    const float* emb   = (const float*)d_in[0];
    const int*   asl   = (const int*)  d_in[1];
    const int*   isqa  = (const int*)  d_in[2];
    const float* fc2W  = (const float*)d_in[3];
    const float* fc2b  = (const float*)d_in[4];
    const float* crfW  = (const float*)d_in[5];
    const float* crfb  = (const float*)d_in[6];
    const float* trans = (const float*)d_in[7];
    float* out = (float*)d_out;

    cudaFuncSetAttribute(scanKernel,
                         cudaFuncAttributeMaxDynamicSharedMemorySize,
                         SCAN_SMEM);

    featsKernel<<<592, 256>>>(emb, fc2W, fc2b, crfW, crfb);
    scanKernel<<<32, 256, SCAN_SMEM>>>(trans, asl, isqa, out);
}

// round 12
// speedup vs baseline: 2.6362x; 1.1426x over previous
#include <cuda_runtime.h>
#include <cstdint>
#include <math.h>

#define H      768
#define TT     4
#define NB     64
#define S1     513
#define S      512
#define NBB    4          // batches per scan block

// Output layout (float32), reference tuple order:
// isqa_pred(64) | crf_pred(64*512) | isqa_loss(1) | crf_loss(1) | tags(64*512) | IsQA(64)
#define OUT_ISQA_PRED 0
#define OUT_CRF_PRED  64
#define OUT_ISQA_LOSS 32832
#define OUT_CRF_LOSS  32833
#define OUT_TAGS      32834
#define OUT_ISQA      65602

typedef unsigned long long ull;

// Static device scratch (no allocation allowed)
__device__ float    g_feats[NB * S * TT];   // (b, t, state), float4 per (b,t)
__device__ float    g_isqa_logits[NB * 2];
__device__ float    g_accCrf, g_accIsqa;
__device__ unsigned g_cnt;

// ---- packed f32x2 helpers (sm_103a) ----
__device__ __forceinline__ ull f2_pack(float x, float y) {
    ull r; asm("mov.b64 %0, {%1, %2};" : "=l"(r) : "f"(x), "f"(y)); return r;
}
__device__ __forceinline__ ull f2_bcast(float x) {
    ull r; asm("mov.b64 %0, {%1, %1};" : "=l"(r) : "f"(x)); return r;
}
__device__ __forceinline__ float2 f2_get(ull v) {
    float2 r; asm("mov.b64 {%0, %1}, %2;" : "=f"(r.x), "=f"(r.y) : "l"(v)); return r;
}
__device__ __forceinline__ ull f2_add(ull a, ull b) {
    ull d; asm("add.rn.f32x2 %0, %1, %2;" : "=l"(d) : "l"(a), "l"(b)); return d;
}
__device__ __forceinline__ ull f2_mul(ull a, ull b) {
    ull d; asm("mul.rn.f32x2 %0, %1, %2;" : "=l"(d) : "l"(a), "l"(b)); return d;
}
__device__ __forceinline__ ull f2_fma(ull a, ull b, ull c) {
    ull d; asm("fma.rn.f32x2 %0, %1, %2, %3;" : "=l"(d) : "l"(a), "l"(b), "l"(c)); return d;
}

// ---------------------------------------------------------------------------
// Kernel A v2: 4 rows per warp sharing weight loads; 16-value butterfly
// reduction (16 SHFLs instead of 80); dedicated CLS blocks.
//   blocks [0,512):   main. group g = 2 per warp (grid-stride), group =
//                     (batch b, 4 consecutive s in [1,513))
//   blocks [512,520): CLS. warp c computes isqa_logits[c]
// ---------------------------------------------------------------------------
#define FEAT_MAIN_BLOCKS 512
#define FEAT_BLOCKS      520

__global__ void __launch_bounds__(256) featsKernel(
    const float* __restrict__ emb,
    const float* __restrict__ fc2W, const float* __restrict__ fc2b,
    const float* __restrict__ crfW, const float* __restrict__ crfb)
{
    if (blockIdx.x == 0 && threadIdx.x == 0) {
        g_cnt = 0u; g_accCrf = 0.f; g_accIsqa = 0.f;
    }

    __shared__ float Wsh[6 * H];   // rows 0-3 crf_W, 4-5 fc2_W
    __shared__ float bsh[8];
    for (int i = threadIdx.x; i < 6 * H; i += 256) {
        Wsh[i] = (i < 4 * H) ? crfW[i] : fc2W[i - 4 * H];
    }
    if (threadIdx.x < 8) {
        int r = threadIdx.x;
        bsh[r] = (r < 4) ? crfb[r] : ((r < 6) ? fc2b[r - 4] : 0.f);
    }
    __syncthreads();

    int warp = threadIdx.x >> 5, lane = threadIdx.x & 31;
    const float4* W4 = (const float4*)Wsh;       // 192 float4 per row
    const float4* E4 = (const float4*)emb;

    if (blockIdx.x < FEAT_MAIN_BLOCKS) {
        // groups: 8192 total = 64 batches x 128 (4-row groups); 2 per warp
        for (int g = blockIdx.x * 8 + warp; g < 8192; g += FEAT_MAIN_BLOCKS * 8) {
            int b = g >> 7, k = g & 127;
            int s0 = 1 + 4 * k;
            const float4* e0p = E4 + (size_t)(b * S1 + s0 + 0) * 192;
            const float4* e1p = E4 + (size_t)(b * S1 + s0 + 1) * 192;
            const float4* e2p = E4 + (size_t)(b * S1 + s0 + 2) * 192;
            const float4* e3p = E4 + (size_t)(b * S1 + s0 + 3) * 192;

            float a[16];
            #pragma unroll
            for (int q = 0; q < 16; q++) a[q] = 0.f;

            #pragma unroll 2
            for (int i = 0; i < 6; i++) {
                int idx = lane + 32 * i;
                float4 e0 = e0p[idx], e1 = e1p[idx], e2 = e2p[idx], e3 = e3p[idx];
                float4 w0 = W4[idx], w1 = W4[192 + idx];
                float4 w2 = W4[384 + idx], w3 = W4[576 + idx];
#define DOT4(E, W) ((E).x*(W).x + (E).y*(W).y + (E).z*(W).z + (E).w*(W).w)
                a[0]  += DOT4(e0, w0); a[1]  += DOT4(e0, w1);
                a[2]  += DOT4(e0, w2); a[3]  += DOT4(e0, w3);
                a[4]  += DOT4(e1, w0); a[5]  += DOT4(e1, w1);
                a[6]  += DOT4(e1, w2); a[7]  += DOT4(e1, w3);
                a[8]  += DOT4(e2, w0); a[9]  += DOT4(e2, w1);
                a[10] += DOT4(e2, w2); a[11] += DOT4(e2, w3);
                a[12] += DOT4(e3, w0); a[13] += DOT4(e3, w1);
                a[14] += DOT4(e3, w2); a[15] += DOT4(e3, w3);
#undef DOT4
            }

            // multi-value butterfly: 16 values -> one output per lane pair
            #pragma unroll
            for (int q = 0; q < 8; q++) {
                float snd = (lane & 16) ? a[q] : a[q + 8];
                float rcv = __shfl_xor_sync(0xffffffffu, snd, 16);
                a[q] = ((lane & 16) ? a[q + 8] : a[q]) + rcv;
            }
            #pragma unroll
            for (int q = 0; q < 4; q++) {
                float snd = (lane & 8) ? a[q] : a[q + 4];
                float rcv = __shfl_xor_sync(0xffffffffu, snd, 8);
                a[q] = ((lane & 8) ? a[q + 4] : a[q]) + rcv;
            }
            #pragma unroll
            for (int q = 0; q < 2; q++) {
                float snd = (lane & 4) ? a[q] : a[q + 2];
                float rcv = __shfl_xor_sync(0xffffffffu, snd, 4);
                a[q] = ((lane & 4) ? a[q + 2] : a[q]) + rcv;
            }
            {
                float snd = (lane & 2) ? a[0] : a[1];
                float rcv = __shfl_xor_sync(0xffffffffu, snd, 2);
                a[0] = ((lane & 2) ? a[1] : a[0]) + rcv;
            }
            a[0] += __shfl_xor_sync(0xffffffffu, a[0], 1);

            int kout = (lane >> 1) & 15;
            int r = kout >> 2, j = kout & 3;
            if ((lane & 1) == 0) {
                g_feats[((size_t)b * S + (s0 - 1 + r)) * TT + j] = a[0] + bsh[j];
            }
        }
    } else {
        // CLS: warp c handles batch c
        int c = (blockIdx.x - FEAT_MAIN_BLOCKS) * 8 + warp;   // 0..63
        const float4* e = E4 + (size_t)(c * S1) * 192;
        float p0 = 0.f, p1 = 0.f;
        #pragma unroll
        for (int i = 0; i < 6; i++) {
            int idx = lane + 32 * i;
            float4 v = e[idx];
            float4 w4 = W4[768 + idx], w5 = W4[960 + idx];
            p0 += v.x * w4.x + v.y * w4.y + v.z * w4.z + v.w * w4.w;
            p1 += v.x * w5.x + v.y * w5.y + v.z * w5.z + v.w * w5.w;
        }
        #pragma unroll
        for (int off = 16; off; off >>= 1) {
            p0 += __shfl_xor_sync(0xffffffffu, p0, off);
            p1 += __shfl_xor_sync(0xffffffffu, p1, off);
        }
        if (lane == 0) {
            g_isqa_logits[c * 2 + 0] = p0 + bsh[4];
            g_isqa_logits[c * 2 + 1] = p1 + bsh[5];
        }
    }
}

// ---------------------------------------------------------------------------
// Kernel B: 32 blocks x 256 threads, 4 batches per block.
//   blocks 0-15  (viterbi role): sequential Viterbi with packed f32x2 adds
//     (bit-exact: lanewise RN adds + exact max), delta stored every step;
//     gold+tags concurrent; parallel backpointer recompute + chunk-parallel
//     backtrace; coalesced writeout.
//   blocks 16-31 (forward role): linear-domain log-partition with packed
//     f32x2 matvec + power-of-2 renorm -> Z; CLS/isqa head + losses.
// ---------------------------------------------------------------------------
#define SCAN_SMEM ((4096 + 512) * 16)   // FL 32KB + DD 32KB + PRED 8KB

__global__ void __launch_bounds__(256, 1) scanKernel(
    const float* __restrict__ trans,
    const int*   __restrict__ asl,
    const int*   __restrict__ isqa_in,
    float* __restrict__ out)
{
    extern __shared__ float4 sm4[];
    float4* FL    = sm4;                 // log feats (viterbi) / exp feats (fwd)
    float4* DD    = sm4 + 2048;
    float4* PRED4 = sm4 + 4096;
    float*  PRED  = (float*)PRED4;
    __shared__ float    aux[8];
    __shared__ unsigned PATHS[NBB * 32 * 4];   // [bb][chunk][entry] packed path
    __shared__ int      ESEL[NBB * 32];        // chosen entry per chunk

    int tid  = threadIdx.x;
    int warp = tid >> 5, lane = tid & 31;
    bool isFwd = blockIdx.x >= 16;
    int bb0 = (blockIdx.x & 15) * NBB;
    const float4* gf = (const float4*)g_feats + (size_t)bb0 * S;

    // ---------------- staging ----------------
    if (!isFwd) {
        for (int v = tid; v < NBB * S; v += 256) {
            int bbv = v >> 9, t = v & 511;
            FL[t * NBB + bbv] = gf[bbv * S + t];
        }
    } else {
        for (int v = tid; v < NBB * S; v += 256) {
            int bbv = v >> 9, t = v & 511;
            float4 f = gf[bbv * S + t];
            FL[t * NBB + bbv] = make_float4(__expf(f.x), __expf(f.y),
                                            __expf(f.z), __expf(f.w));
        }
    }
    __syncthreads();

    if (!isFwd) {
        // ============== VITERBI ROLE ==============
        if (warp == 0 && lane < NBB) {
            int bb = lane;
            // packed transition columns: T01[j]=(t0j,t1j), T23[j]=(t2j,t3j)
            ull T01_0 = f2_pack(trans[0], trans[4]);
            ull T01_1 = f2_pack(trans[1], trans[5]);
            ull T01_2 = f2_pack(trans[2], trans[6]);
            ull T01_3 = f2_pack(trans[3], trans[7]);
            ull T23_0 = f2_pack(trans[8],  trans[12]);
            ull T23_1 = f2_pack(trans[9],  trans[13]);
            ull T23_2 = f2_pack(trans[10], trans[14]);
            ull T23_3 = f2_pack(trans[11], trans[15]);

            float4 f0 = FL[bb];
            float d0 = f0.x + trans[8],  d1 = f0.y + trans[9];   // START row=2
            float d2 = f0.z + trans[10], d3 = f0.w + trans[11];
            ull D01 = f2_pack(d0, d1), D23 = f2_pack(d2, d3);
            DD[bb] = make_float4(d0, d1, d2, d3);
            float4 fc = FL[NBB + bb];                  // prefetch t=1
#define VSTEP(FV, T)                                                          \
            {                                                                 \
                float2 p0 = f2_get(f2_add(D01, T01_0));                       \
                float2 q0 = f2_get(f2_add(D23, T23_0));                       \
                float2 p1 = f2_get(f2_add(D01, T01_1));                       \
                float2 q1 = f2_get(f2_add(D23, T23_1));                       \
                float2 p2 = f2_get(f2_add(D01, T01_2));                       \
                float2 q2 = f2_get(f2_add(D23, T23_2));                       \
                float2 p3 = f2_get(f2_add(D01, T01_3));                       \
                float2 q3 = f2_get(f2_add(D23, T23_3));                       \
                float n0 = fmaxf(fmaxf(p0.x, p0.y), fmaxf(q0.x, q0.y)) + (FV).x; \
                float n1 = fmaxf(fmaxf(p1.x, p1.y), fmaxf(q1.x, q1.y)) + (FV).y; \
                float n2 = fmaxf(fmaxf(p2.x, p2.y), fmaxf(q2.x, q2.y)) + (FV).z; \
                float n3 = fmaxf(fmaxf(p3.x, p3.y), fmaxf(q3.x, q3.y)) + (FV).w; \
                D01 = f2_pack(n0, n1); D23 = f2_pack(n2, n3);                 \
                DD[(T) * NBB + bb] = make_float4(n0, n1, n2, n3);             \
            }
            #pragma unroll 8
            for (int t = 1; t < S - 1; ++t) {
                float4 f = fc;
                fc = FL[(t + 1) * NBB + bb];
                VSTEP(f, t);
            }
            VSTEP(fc, S - 1);
#undef VSTEP
        } else if (warp >= 1 && warp <= NBB) {
            // gold score + tags for batch (warp-1), concurrent with seq warp
            int bb = warp - 1, b = bb0 + bb;
            const int* tg = asl + b * S1 + 1;
            float acc = 0.f;
            for (int t = lane; t < S; t += 32) {
                int tag = tg[t];
                acc += ((const float*)&FL[t * NBB + bb])[tag];
                out[OUT_TAGS + b * S + t] = (float)tag;
                if (t < S - 1) acc += trans[tag * TT + tg[t + 1]];
            }
            #pragma unroll
            for (int off = 16; off; off >>= 1)
                acc += __shfl_down_sync(0xffffffffu, acc, off);
            if (lane == 0)
                aux[bb] = acc + trans[2 * TT + tg[0]]
                              + trans[tg[S - 1] * TT + 3];
        }
        __syncthreads();

        // ---- parallel backpointer recompute + per-chunk path decode ----
        if (tid < 128) {
            int w = tid >> 2, bb = tid & 3;
            float t00 = trans[0],  t01 = trans[1],  t02 = trans[2],  t03 = trans[3];
            float t10 = trans[4],  t11 = trans[5],  t12 = trans[6],  t13 = trans[7];
            float t20 = trans[8],  t21 = trans[9],  t22 = trans[10], t23 = trans[11];
            float t30 = trans[12], t31 = trans[13], t32 = trans[14], t33 = trans[15];
            unsigned r0 = 0, r1 = 0, r2 = 0, r3 = 0;
            #pragma unroll
            for (int k = 0; k < 16; ++k) {
                int t = w * 16 + k;
                if (t == 0) continue;
                float4 d = DD[(t - 1) * NBB + bb];
                {
                    float v0 = d.x + t00, v1 = d.y + t10, v2 = d.z + t20, v3 = d.w + t30;
                    float best = v0; int bi = 0;
                    if (v1 > best) { best = v1; bi = 1; }
                    if (v2 > best) { best = v2; bi = 2; }
                    if (v3 > best) { best = v3; bi = 3; }
                    r0 |= (unsigned)bi << (2 * k);
                }
                {
                    float v0 = d.x + t01, v1 = d.y + t11, v2 = d.z + t21, v3 = d.w + t31;
                    float best = v0; int bi = 0;
                    if (v1 > best) { best = v1; bi = 1; }
                    if (v2 > best) { best = v2; bi = 2; }
                    if (v3 > best) { best = v3; bi = 3; }
                    r1 |= (unsigned)bi << (2 * k);
                }
                {
                    float v0 = d.x + t02, v1 = d.y + t12, v2 = d.z + t22, v3 = d.w + t32;
                    float best = v0; int bi = 0;
                    if (v1 > best) { best = v1; bi = 1; }
                    if (v2 > best) { best = v2; bi = 2; }
                    if (v3 > best) { best = v3; bi = 3; }
                    r2 |= (unsigned)bi << (2 * k);
                }
                {
                    float v0 = d.x + t03, v1 = d.y + t13, v2 = d.z + t23, v3 = d.w + t33;
                    float best = v0; int bi = 0;
                    if (v1 > best) { best = v1; bi = 1; }
                    if (v2 > best) { best = v2; bi = 2; }
                    if (v3 > best) { best = v3; bi = 3; }
                    r3 |= (unsigned)bi << (2 * k);
                }
            }
            // decode all 4 possible entry states through this chunk
            #pragma unroll
            for (int e = 0; e < 4; ++e) {
                int cur = e; unsigned path = 0;
                #pragma unroll
                for (int k = 15; k >= 0; --k) {
                    unsigned word = (cur == 0) ? r0 : (cur == 1) ? r1
                                  : (cur == 2) ? r2 : r3;
                    cur = (int)((word >> (2 * k)) & 3u);
                    path |= (unsigned)cur << (2 * k);
                }
                PATHS[(bb * 32 + w) * 4 + e] = path;
            }
        }
        __syncthreads();

        // ---- chunk-chain: pick entry state per chunk (one thread/batch) ----
        if (tid < NBB) {
            int bb = tid;
            float4 dl = DD[(S - 1) * NBB + bb];
            float s0 = dl.x + trans[3],  s1 = dl.y + trans[7];
            float s2 = dl.z + trans[11], s3 = dl.w + trans[15];
            float best = s0; int cur = 0;
            if (s1 > best) { best = s1; cur = 1; }
            if (s2 > best) { best = s2; cur = 2; }
            if (s3 > best) { best = s3; cur = 3; }
            PRED[bb * S + S - 1] = (float)cur;
            for (int w = 31; w >= 0; --w) {
                ESEL[bb * 32 + w] = cur;
                cur = (int)(PATHS[(bb * 32 + w) * 4 + cur] & 3u);
            }
        }
        __syncthreads();

        // ---- parallel path writeout into PRED smem ----
        if (tid < 128) {
            int w = tid >> 2, bb = tid & 3;
            int e = ESEL[bb * 32 + w];
            unsigned path = PATHS[(bb * 32 + w) * 4 + e];
            #pragma unroll
            for (int k = 15; k >= 0; --k) {
                int t = w * 16 + k;
                if (t == 0) continue;
                PRED[bb * S + t - 1] = (float)((path >> (2 * k)) & 3u);
            }
        }
        __syncthreads();

        // ---- coalesced pred writeout ----
        for (int v = tid; v < NBB * (S / 4); v += 256) {
            int bbv = v >> 7, idx = v & 127;
            ((float4*)(out + OUT_CRF_PRED + (size_t)(bb0 + bbv) * S))[idx]
                = PRED4[bbv * (S / 4) + idx];
        }

        // ---- gold accumulation + finalize ----
        if (tid == 0) {
            float gsum = aux[0] + aux[1] + aux[2] + aux[3];
            atomicAdd(&g_accCrf, -gsum);
            __threadfence();
            unsigned old = atomicAdd(&g_cnt, 1u);
            if (old == 31u) {
                __threadfence();
                out[OUT_CRF_LOSS]  = (*(volatile float*)&g_accCrf)  * (1.f / 64.f);
                out[OUT_ISQA_LOSS] = (*(volatile float*)&g_accIsqa) * (1.f / 64.f);
            }
        }
    } else {
        // ============== FORWARD ROLE ==============
        if (warp == 0 && lane < NBB) {
            int bb = lane;
            // packed E rows: EA01[i]=(E[i][0],E[i][1]), EA23[i]=(E[i][2],E[i][3])
            ull EA01_0 = f2_pack(__expf(trans[0]),  __expf(trans[1]));
            ull EA23_0 = f2_pack(__expf(trans[2]),  __expf(trans[3]));
            ull EA01_1 = f2_pack(__expf(trans[4]),  __expf(trans[5]));
            ull EA23_1 = f2_pack(__expf(trans[6]),  __expf(trans[7]));
            ull EA01_2 = f2_pack(__expf(trans[8]),  __expf(trans[9]));
            ull EA23_2 = f2_pack(__expf(trans[10]), __expf(trans[11]));
            ull EA01_3 = f2_pack(__expf(trans[12]), __expf(trans[13]));
            ull EA23_3 = f2_pack(__expf(trans[14]), __expf(trans[15]));
            float P0 = __expf(trans[3]),  P1 = __expf(trans[7]);
            float P2 = __expf(trans[11]), P3 = __expf(trans[15]);

            float4 f0 = FL[bb];
            ull S01 = f2_pack(f0.x * __expf(trans[8]),  f0.y * __expf(trans[9]));
            ull S23 = f2_pack(f0.z * __expf(trans[10]), f0.w * __expf(trans[11]));
            int eAcc = 0;
#define FSTEP(EF)                                                             \
            {                                                                 \
                float2 s01 = f2_get(S01), s23 = f2_get(S23);                  \
                ull B0 = f2_bcast(s01.x), B1 = f2_bcast(s01.y);               \
                ull B2 = f2_bcast(s23.x), B3 = f2_bcast(s23.y);               \
                ull N01 = f2_mul(B0, EA01_0);                                 \
                N01 = f2_fma(B1, EA01_1, N01);                                \
                N01 = f2_fma(B2, EA01_2, N01);                                \
                N01 = f2_fma(B3, EA01_3, N01);                                \
                ull N23 = f2_mul(B0, EA23_0);                                 \
                N23 = f2_fma(B1, EA23_1, N23);                                \
                N23 = f2_fma(B2, EA23_2, N23);                                \
                N23 = f2_fma(B3, EA23_3, N23);                                \
                S01 = f2_mul(N01, f2_pack((EF).x, (EF).y));                   \
                S23 = f2_mul(N23, f2_pack((EF).z, (EF).w));                   \
            }
            int t = 1;
            float4 fc = FL[NBB + bb];                  // prefetch t=1
            for (int w = 0; w < 63; ++w) {
                #pragma unroll
                for (int k = 0; k < 8; ++k, ++t) {
                    float4 ef = fc;
                    fc = FL[(t + 1) * NBB + bb];
                    FSTEP(ef);
                }
                // exact power-of-2 renorm (all s > 0)
                float2 s01 = f2_get(S01);
                int e = (__float_as_int(s01.x) >> 23) & 255;
                eAcc += e - 127;
                ull SC = f2_bcast(__int_as_float((unsigned)(254 - e) << 23));
                S01 = f2_mul(S01, SC); S23 = f2_mul(S23, SC);
            }
            #pragma unroll
            for (int k = 0; k < 7; ++k, ++t) {         // t = 505..511
                float4 ef = fc;
                if (t < S - 1) fc = FL[(t + 1) * NBB + bb];
                FSTEP(ef);
            }
#undef FSTEP
            float2 s01 = f2_get(S01), s23 = f2_get(S23);
            float zt = (s01.x * P0 + s01.y * P1) + (s23.x * P2 + s23.y * P3);
            float Z = __logf(zt) + (float)eAcc * 0.693147180559945f;
            aux[bb] = Z;

            // CLS / isqa head for this batch
            int b = bb0 + bb;
            float l0 = g_isqa_logits[b * 2 + 0];
            float l1 = g_isqa_logits[b * 2 + 1];
            float m = fmaxf(l0, l1);
            float lse = m + __logf(__expf(l0 - m) + __expf(l1 - m));
            int y = isqa_in[b];
            aux[4 + bb] = lse - (y ? l1 : l0);
            out[OUT_ISQA_PRED + b] = (l1 > l0) ? 1.f : 0.f;
            out[OUT_ISQA + b] = (float)y;

            __syncwarp(0xFu);
            if (lane == 0) {
                atomicAdd(&g_accCrf,  aux[0] + aux[1] + aux[2] + aux[3]);
                atomicAdd(&g_accIsqa, aux[4] + aux[5] + aux[6] + aux[7]);
                __threadfence();
                unsigned old = atomicAdd(&g_cnt, 1u);
                if (old == 31u) {
                    __threadfence();
                    out[OUT_CRF_LOSS]  = (*(volatile float*)&g_accCrf)  * (1.f / 64.f);
                    out[OUT_ISQA_LOSS] = (*(volatile float*)&g_accIsqa) * (1.f / 64.f);
                }
            }
        }
    }
}

// ---------------------------------------------------------------------------
extern "C" void kernel_launch(void* const* d_in, const int* in_sizes, int n_in,
                              void* d_out, int out_size)
{
    const float* emb   = (const float*)d_in[0];
    const int*   asl   = (const int*)  d_in[1];
    const int*   isqa  = (const int*)  d_in[2];
    const float* fc2W  = (const float*)d_in[3];
    const float* fc2b  = (const float*)d_in[4];
    const float* crfW  = (const float*)d_in[5];
    const float* crfb  = (const float*)d_in[6];
    const float* trans = (const float*)d_in[7];
    float* out = (float*)d_out;

    cudaFuncSetAttribute(scanKernel,
                         cudaFuncAttributeMaxDynamicSharedMemorySize,
                         SCAN_SMEM);

    featsKernel<<<FEAT_BLOCKS, 256>>>(emb, fc2W, fc2b, crfW, crfb);
    scanKernel<<<32, 256, SCAN_SMEM>>>(trans, asl, isqa, out);
}